// round 2
// baseline (speedup 1.0000x reference)
#include <cuda_runtime.h>
#include <math.h>

#define NPTS   8192
#define BATCH  2
#define NQ_TOT (2 * BATCH * NPTS)        // 32768 query rows total (both passes)

#define THREADS 128
#define IPT     4                        // queries per thread
#define QPB     (THREADS * IPT)          // 512 queries per block
#define QCHUNKS ((2 * BATCH * NPTS) / QPB)   // 64
#define CHUNKS_PER_PB (NPTS / QPB)       // 16 chunks per (pass,b)
#define JSPLIT  8
#define JLEN    (NPTS / JSPLIT)          // 1024 database points per block
#define JPAIRS  (JLEN / 2)               // 512 packed pairs

// Partial mins: plain stores (no atomics, no init needed). 1 MB, L2-resident.
__device__ float g_partial[JSPLIT][NQ_TOT];

// ---- packed f32x2 helpers --------------------------------------------------
static __device__ __forceinline__ unsigned long long pack2(float lo, float hi) {
    unsigned long long r;
    asm("mov.b64 %0, {%1, %2};" : "=l"(r) : "f"(lo), "f"(hi));
    return r;
}
static __device__ __forceinline__ void unpack2(unsigned long long v, float& lo, float& hi) {
    asm("mov.b64 {%0, %1}, %2;" : "=f"(lo), "=f"(hi) : "l"(v));
}
// FFMA2: two independent f32 FMAs per instruction (sm_103a packed pipe)
static __device__ __forceinline__ unsigned long long fma2(
    unsigned long long a, unsigned long long b, unsigned long long c) {
    unsigned long long d;
    asm("fma.rn.f32x2 %0, %1, %2, %3;" : "=l"(d) : "l"(a), "l"(b), "l"(c));
    return d;
}

// Grid: (QCHUNKS, JSPLIT). Block: 512 queries x 1024 database points.
// Tile layout per j-pair (32B): {-2x0,-2x1,-2y0,-2y1} | {-2z0,-2z1, w0, w1}
// so the inner loop is exactly 3 FFMA2 + 2 FMNMX per 2 pairs.
__global__ void __launch_bounds__(THREADS)
min_kernel(const float* __restrict__ pred, const float* __restrict__ gt) {
    __shared__ float4 tile[2 * JPAIRS];   // 16 KB

    int qblk = blockIdx.x;                 // 0..63
    int pb   = qblk / CHUNKS_PER_PB;       // pass*BATCH + b (uniform per block)
    int pass = pb >> 1;
    int b    = pb & 1;
    int nbase = (qblk % CHUNKS_PER_PB) * QPB;

    const float* qsrc = (pass == 0) ? gt : pred;   // queries
    const float* dsrc = (pass == 0) ? pred : gt;   // database
    int jbase = blockIdx.y * JLEN;

    // Build packed tile straight from raw global input (L2-resident).
    const float* dbase = dsrc + ((long)b * NPTS + jbase) * 3;
    for (int jp = threadIdx.x; jp < JPAIRS; jp += THREADS) {
        const float* p = dbase + 6 * jp;
        float x0 = p[0], y0 = p[1], z0 = p[2];
        float x1 = p[3], y1 = p[4], z1 = p[5];
        tile[2 * jp]     = make_float4(-2.f * x0, -2.f * x1, -2.f * y0, -2.f * y1);
        tile[2 * jp + 1] = make_float4(-2.f * z0, -2.f * z1,
                                       x0 * x0 + y0 * y0 + z0 * z0,
                                       x1 * x1 + y1 * y1 + z1 * z1);
    }
    __syncthreads();

    unsigned long long qx[IPT], qy[IPT], qz[IPT];
    float mlo[IPT], mhi[IPT];
#pragma unroll
    for (int k = 0; k < IPT; k++) {
        int n = nbase + k * THREADS + threadIdx.x;
        const float* q = qsrc + ((long)b * NPTS + n) * 3;
        float x = q[0], y = q[1], z = q[2];
        qx[k] = pack2(x, x); qy[k] = pack2(y, y); qz[k] = pack2(z, z);
        mlo[k] = 3.4e38f; mhi[k] = 3.4e38f;
    }

    const ulonglong2* tu = (const ulonglong2*)tile;
#pragma unroll 4
    for (int jp = 0; jp < JPAIRS; jp++) {
        ulonglong2 P0 = tu[2 * jp];       // {pxx, pyy}
        ulonglong2 P1 = tu[2 * jp + 1];   // {pzz, pww}
#pragma unroll
        for (int k = 0; k < IPT; k++) {
            // packed t = |p|^2 - 2<q,p> for two database points at once
            unsigned long long t =
                fma2(qx[k], P0.x, fma2(qy[k], P0.y, fma2(qz[k], P1.x, P1.y)));
            float tlo, thi;
            unpack2(t, tlo, thi);
            mlo[k] = fminf(mlo[k], tlo);
            mhi[k] = fminf(mhi[k], thi);
        }
    }

#pragma unroll
    for (int k = 0; k < IPT; k++) {
        int q = pass * (BATCH * NPTS) + b * NPTS + nbase + k * THREADS + threadIdx.x;
        g_partial[blockIdx.y][q] = fminf(mlo[k], mhi[k]);
    }
}

__global__ void __launch_bounds__(1024)
reduce_kernel(const float* __restrict__ pred, const float* __restrict__ gt,
              float* __restrict__ out) {
    __shared__ float sbuf[1024];
    int tid = threadIdx.x;
    float s = 0.0f;
    for (int q = tid; q < NQ_TOT; q += 1024) {
        int pass = q / (BATCH * NPTS);
        int r    = q % (BATCH * NPTS);          // b*NPTS + n
        const float* qsrc = (pass == 0) ? gt : pred;
        float x = qsrc[3 * r + 0], y = qsrc[3 * r + 1], z = qsrc[3 * r + 2];
        float g2 = x * x + y * y + z * z;
        float m = g_partial[0][q];
#pragma unroll
        for (int sidx = 1; sidx < JSPLIT; sidx++)
            m = fminf(m, g_partial[sidx][q]);
        s += sqrtf(fmaxf(g2 + m, 0.0f));
    }
    sbuf[tid] = s;
    __syncthreads();
    for (int off = 512; off > 0; off >>= 1) {
        if (tid < off) sbuf[tid] += sbuf[tid + off];
        __syncthreads();
    }
    if (tid == 0) out[0] = sbuf[0] / (float)(BATCH * NPTS);
}

extern "C" void kernel_launch(void* const* d_in, const int* in_sizes, int n_in,
                              void* d_out, int out_size) {
    const float* pred = (const float*)d_in[0];
    const float* gt   = (const float*)d_in[1];
    float* out = (float*)d_out;

    dim3 grid(QCHUNKS, JSPLIT);
    min_kernel<<<grid, THREADS>>>(pred, gt);
    reduce_kernel<<<1, 1024>>>(pred, gt, out);
}